// round 6
// baseline (speedup 1.0000x reference)
#include <cuda_runtime.h>
#include <cstdint>

// CRF forward partition function, linear-domain reformulation, R4 (resubmit;
// R5 bench attempt failed on infra, not on the kernel).
// R4 change vs R3: TWO independent batches per warp, steps fused pairwise.
// The two scan chains interleave in the SASS stream, hiding each other's
// RAW latency (LDS 29 / FFMA 4 chains); one __syncwarp per pair. E rows
// (batch-invariant) stay in registers once. tt loop NOT unrolled so the
// pair body stays resident in L0 I-cache.
// Numerics unchanged: per-step exact power-of-2 renorm with one-step lag,
// PAD chain decoupled analytically.

#define KK 48
#define TT 1024
#define BB 512
#define CH 16
#define NCHUNK (TT / CH)
#define PAD_TAG 45
#define STOP_TAG 47
#define NEGV (-10000.0f)
#define LOG2E 1.4426950408889634f
#define LN2F 0.6931471805599453f

__device__ __forceinline__ float ex2(float x) {
    float r; asm("ex2.approx.f32 %0, %1;" : "=f"(r) : "f"(x)); return r;
}
__device__ __forceinline__ float lg2(float x) {
    float r; asm("lg2.approx.f32 %0, %1;" : "=f"(r) : "f"(x)); return r;
}
__device__ __forceinline__ unsigned long long pk2(float lo, float hi) {
    unsigned long long r;
    asm("mov.b64 %0, {%1, %2};" : "=l"(r) : "f"(lo), "f"(hi));
    return r;
}
__device__ __forceinline__ void upk2(float& lo, float& hi, unsigned long long v) {
    asm("mov.b64 {%0, %1}, %2;" : "=f"(lo), "=f"(hi) : "l"(v));
}
__device__ __forceinline__ void ffma2(unsigned long long& acc,
                                      unsigned long long a, unsigned long long b) {
    asm("fma.rn.f32x2 %0, %1, %2, %0;" : "+l"(acc) : "l"(a), "l"(b));
}
__device__ __forceinline__ unsigned long long add2(unsigned long long a,
                                                   unsigned long long b) {
    unsigned long long r;
    asm("add.rn.f32x2 %0, %1, %2;" : "=l"(r) : "l"(a), "l"(b));
    return r;
}
__device__ __forceinline__ void cpasync16(uint32_t saddr, const void* gaddr) {
    asm volatile("cp.async.cg.shared.global [%0], [%1], 16;"
                 :: "r"(saddr), "l"(gaddr));
}
__device__ __forceinline__ void cpcommit() {
    asm volatile("cp.async.commit_group;");
}
__device__ __forceinline__ void cpwait1() {
    asm volatile("cp.async.wait_group 1;");
}

__global__ __launch_bounds__(64, 1)
void crf_fwd_kernel(const float* __restrict__ h_tag,
                    const float* __restrict__ mask,
                    const float* __restrict__ trans,
                    float* __restrict__ out) {
    __shared__ __align__(16) float trs[KK * KK];
    __shared__ __align__(16) float pd[2][2][96];            // [warp][batch]
    __shared__ __align__(16) float sm_em[2][2][2][CH * KK]; // [warp][batch][buf]
    __shared__ __align__(16) float sm_mk[2][2][2][CH];

    const int tid  = threadIdx.x;
    const int wid  = tid >> 5;
    const int lane = tid & 31;
    const int bA   = blockIdx.x * 4 + wid * 2;
    const int bB   = bA + 1;

    const float* embA = h_tag + (size_t)bA * TT * KK;
    const float* embB = h_tag + (size_t)bB * TT * KK;
    const float* mkbA = mask + (size_t)bA * TT;
    const float* mkbB = mask + (size_t)bB * TT;

    // ---- deep prefetch: both batches, one commit group per chunk ----
    auto issue_chunk = [&](int cc) {
        const int buf = cc & 1;
#pragma unroll
        for (int ba = 0; ba < 2; ++ba) {
            const float* src = (ba ? embB : embA) + cc * (CH * KK);
            uint32_t dst =
                (uint32_t)__cvta_generic_to_shared(&sm_em[wid][ba][buf][0]);
#pragma unroll
            for (int it = 0; it < (CH * KK) / (32 * 4); ++it) {  // 6 iters
                int off = (it * 32 + lane) * 4;
                cpasync16(dst + (uint32_t)off * 4u, src + off);
            }
            if (lane < CH / 4) {
                uint32_t md =
                    (uint32_t)__cvta_generic_to_shared(&sm_mk[wid][ba][buf][0]);
                cpasync16(md + (uint32_t)lane * 16u,
                          (ba ? mkbB : mkbA) + cc * CH + lane * 4);
            }
        }
        cpcommit();
    };
    issue_chunk(0);
    issue_chunk(1);

    // Stage trans coalesced into shared (overlaps cp.async flight).
    for (int i = tid; i < KK * KK; i += 64) trs[i] = trans[i];
    __syncthreads();

    const int  i1   = lane;
    const bool has2 = (lane < 16);
    const int  i2   = has2 ? (lane + 32) : 0;   // clamped for safe loads

    // E rows in registers: Ep[j] = packed(exp(trans[i1][j]), exp(trans[i2][j]))
    unsigned long long Ep[KK - 1];              // j = 0..46
    float rs1 = 0.f, rs2 = 0.f, es1 = 0.f, es2 = 0.f;
#pragma unroll
    for (int j = 0; j < KK; ++j) {
        float e1 = ex2(trs[i1 * KK + j] * LOG2E);
        float e2 = has2 ? ex2(trs[i2 * KK + j] * LOG2E) : 0.f;
        if (j < KK - 1) Ep[j] = pk2(e1, e2);
        rs1 += e1; rs2 += e2;
        if (j == STOP_TAG) { es1 = e1; es2 = e2; }
    }
    const float ES1 = ex2(trs[STOP_TAG * KK + i1] * LOG2E);
    const float ES2 = has2 ? ex2(trs[STOP_TAG * KK + i2] * LOG2E) : 0.f;

    // Exact init at group scale C0 = NEG*log2e:
    // p_i(1) = g_i * ( [i != PAD] + rowsum_i - E[i][STOP] )
    const float base1 = ((i1 == PAD_TAG) ? 0.f : 1.f) + rs1 - es1;
    const float base2 = ((has2 && i2 == PAD_TAG) ? 0.f : 1.f) + rs2 - es2;

    float* pdA = pd[wid][0];
    float* pdB = pd[wid][1];

    float p1A, p2A, p1B, p2B, padaccA, padaccB;
    int cA = 0, cB = 0, eprevA, eprevB;
    {
        float emA1 = embA[i1], emA2 = has2 ? embA[i2] : 0.f;
        float emB1 = embB[i1], emB2 = has2 ? embB[i2] : 0.f;
        p1A = ex2(emA1 * LOG2E) * base1;
        p2A = has2 ? (ex2(emA2 * LOG2E) * base2) : 0.f;
        p1B = ex2(emB1 * LOG2E) * base1;
        p2B = has2 ? (ex2(emB2 * LOG2E) * base2) : 0.f;
        padaccA = emA2;       // lane 13 (i2==45==PAD) is meaningful
        padaccB = emB2;

        *(unsigned long long*)&pdA[2 * i1] = pk2(p1A, p1A);
        *(unsigned long long*)&pdB[2 * i1] = pk2(p1B, p1B);
        if (has2) {
            *(unsigned long long*)&pdA[2 * i2] = pk2(p2A, p2A);
            *(unsigned long long*)&pdB[2 * i2] = pk2(p2B, p2B);
        }
        float zpA = __shfl_sync(0xffffffffu, p1A, 0);
        float zpB = __shfl_sync(0xffffffffu, p1B, 0);
        int ea = (__float_as_int(zpA) >> 23) & 255;
        int eb = (__float_as_int(zpB) >> 23) & 255;
        eprevA = (ea == 0) ? 0 : (ea - 127);
        eprevB = (eb == 0) ? 0 : (eb - 127);
        __syncwarp();
    }

    // ---- fused pair step: two independent chains interleaved ----
    auto step_pair = [&](const float* __restrict__ eAb,
                         const float* __restrict__ eBb,
                         const float* __restrict__ mAb,
                         const float* __restrict__ mBb, int tt) {
        const float cemA1 = eAb[tt * KK + i1];
        const float cemA2 = eAb[tt * KK + i2];
        const float cemB1 = eBb[tt * KK + i1];
        const float cemB2 = eBb[tt * KK + i2];
        const bool  mA = (mAb[tt] != 0.0f);
        const bool  mB = (mBb[tt] != 0.0f);

        const float neA = -(float)eprevA;
        const float neB = -(float)eprevB;
        const float gA1 = ex2(fmaf(cemA1, LOG2E, neA));
        const float gA2 = ex2(fmaf(cemA2, LOG2E, neA));
        const float gB1 = ex2(fmaf(cemB1, LOG2E, neB));
        const float gB2 = ex2(fmaf(cemB2, LOG2E, neB));

        unsigned long long a0 = 0ull, a1 = 0ull, a2 = 0ull, a3 = 0ull;
        unsigned long long b0 = 0ull, b1 = 0ull, b2 = 0ull, b3 = 0ull;
#pragma unroll
        for (int j = 0; j < 44; j += 4) {
            ulonglong2 pA0 = *(const ulonglong2*)(pdA + 2 * j);
            ulonglong2 pB0 = *(const ulonglong2*)(pdB + 2 * j);
            ulonglong2 pA1 = *(const ulonglong2*)(pdA + 2 * j + 4);
            ulonglong2 pB1 = *(const ulonglong2*)(pdB + 2 * j + 4);
            ffma2(a0, pA0.x, Ep[j]);     ffma2(b0, pB0.x, Ep[j]);
            ffma2(a1, pA0.y, Ep[j + 1]); ffma2(b1, pB0.y, Ep[j + 1]);
            ffma2(a2, pA1.x, Ep[j + 2]); ffma2(b2, pB1.x, Ep[j + 2]);
            ffma2(a3, pA1.y, Ep[j + 3]); ffma2(b3, pB1.y, Ep[j + 3]);
        }
        {   // tail j = 44, 46 (cols 45/PAD and 47/STOP carry no usable mass)
            unsigned long long pA44 = *(const unsigned long long*)(pdA + 88);
            unsigned long long pB44 = *(const unsigned long long*)(pdB + 88);
            unsigned long long pA46 = *(const unsigned long long*)(pdA + 92);
            unsigned long long pB46 = *(const unsigned long long*)(pdB + 92);
            ffma2(a0, pA44, Ep[44]);  ffma2(b0, pB44, Ep[44]);
            ffma2(a1, pA46, Ep[46]);  ffma2(b1, pB46, Ep[46]);
        }
        const unsigned long long qsA = add2(add2(a0, a1), add2(a2, a3));
        const unsigned long long qsB = add2(add2(b0, b1), add2(b2, b3));
        float qa, qb; upk2(qa, qb, qsA);
        float ra, rb; upk2(ra, rb, qsB);

        p1A = mA ? (qa * gA1) : p1A;
        p2A = mA ? (qb * gA2) : p2A;
        p1B = mB ? (ra * gB1) : p1B;
        p2B = mB ? (rb * gB2) : p2B;
        padaccA += mA ? cemA2 : 0.f;
        padaccB += mB ? cemB2 : 0.f;
        cA += mA ? eprevA : 0;
        cB += mB ? eprevB : 0;

        // Lagged exponent proxies (consumed next pair; latency hidden).
        const float zpA = __shfl_sync(0xffffffffu, p1A, 0);
        const float zpB = __shfl_sync(0xffffffffu, p1B, 0);

        *(unsigned long long*)&pdA[2 * i1] = pk2(p1A, p1A);
        *(unsigned long long*)&pdB[2 * i1] = pk2(p1B, p1B);
        if (has2) {
            *(unsigned long long*)&pdA[2 * i2] = pk2(p2A, p2A);
            *(unsigned long long*)&pdB[2 * i2] = pk2(p2B, p2B);
        }
        __syncwarp();

        const int ea = (__float_as_int(zpA) >> 23) & 255;
        const int eb = (__float_as_int(zpB) >> 23) & 255;
        eprevA = (ea == 0) ? 0 : (ea - 127);
        eprevB = (eb == 0) ? 0 : (eb - 127);
    };

    // ---- chunk 0 (steps 1..15; step 0 handled by init) ----
    {
        cpwait1();
        __syncwarp();
        const float* eAb = sm_em[wid][0][0];
        const float* eBb = sm_em[wid][1][0];
        const float* mAb = sm_mk[wid][0][0];
        const float* mBb = sm_mk[wid][1][0];
#pragma unroll 1
        for (int tt = 1; tt < CH; ++tt) step_pair(eAb, eBb, mAb, mBb, tt);
        issue_chunk(2);
    }

    // ---- chunks 1..63 ----
#pragma unroll 1
    for (int cc = 1; cc < NCHUNK; ++cc) {
        cpwait1();
        __syncwarp();
        const int buf = cc & 1;
        const float* eAb = sm_em[wid][0][buf];
        const float* eBb = sm_em[wid][1][buf];
        const float* mAb = sm_mk[wid][0][buf];
        const float* mBb = sm_mk[wid][1][buf];
#pragma unroll 1
        for (int tt = 0; tt < CH; ++tt) step_pair(eAb, eBb, mAb, mBb, tt);
        if (cc + 2 < NCHUNK) issue_chunk(cc + 2);
    }

    // ---- final: lse_j(score_j + trans[STOP][j]) at scale C, merged with
    //      the analytic PAD chain (+ trans[STOP][PAD] = NEG). ----
    float sA = p1A * ES1 + (has2 ? p2A * ES2 : 0.f);
    float sB = p1B * ES1 + (has2 ? p2B * ES2 : 0.f);
#pragma unroll
    for (int o = 16; o > 0; o >>= 1) {
        sA += __shfl_xor_sync(0xffffffffu, sA, o);
        sB += __shfl_xor_sync(0xffffffffu, sB, o);
    }

    const float CA    = NEGV * LOG2E + (float)cA;
    const float CB    = NEGV * LOG2E + (float)cB;
    const float mainA = CA + lg2(sA);
    const float mainB = CB + lg2(sB);
    const float padvA = __shfl_sync(0xffffffffu, padaccA, 13);
    const float padvB = __shfl_sync(0xffffffffu, padaccB, 13);
    const float padA2 = (padvA + NEGV) * LOG2E;
    const float padB2 = (padvB + NEGV) * LOG2E;

    if (lane == 0) {
        float hi = fmaxf(mainA, padA2), lo = fminf(mainA, padA2);
        out[bA] = (hi + lg2(1.0f + ex2(lo - hi))) * LN2F;
        hi = fmaxf(mainB, padB2); lo = fminf(mainB, padB2);
        out[bB] = (hi + lg2(1.0f + ex2(lo - hi))) * LN2F;
    }
}

extern "C" void kernel_launch(void* const* d_in, const int* in_sizes, int n_in,
                              void* d_out, int out_size) {
    const float* h_tag = (const float*)d_in[0];
    const float* mask  = (const float*)d_in[1];
    const float* trans = (const float*)d_in[2];
    float* out = (float*)d_out;
    (void)in_sizes; (void)n_in; (void)out_size;
    crf_fwd_kernel<<<BB / 4, 64>>>(h_tag, mask, trans, out);
}

// round 7
// speedup vs baseline: 1.1453x; 1.1453x over previous
#include <cuda_runtime.h>
#include <cstdint>

// CRF forward partition function, linear-domain reformulation, R6.
// R6 design: warp-PAIR cooperative scan. Two warps (roles 0/1) share one
// batch, splitting the j-reduction: role r owns E columns j = r*24 .. r*24+23
// (24 packed rows = 48 regs -- fits comfortably, unlike R4's 188).
// Per step each warp: 24 FFMA2 + 12 uniform LDS.128, then exchanges its
// per-lane partial via STS.64 / named team barrier / LDS.64; both warps
// redundantly finalize p (identical values; duplicate stores benign).
// 128 CTAs x 256 threads = 1024 warps -> 2 warps on every SMSP of 128 SMs;
// the two warps on an SMSP serve DIFFERENT batches, hiding each other's
// RAW/bar stalls. Columns j=45,47 are included with exactly-zero E entries
// (ex2 underflow), making both roles' bodies fully uniform.
// Numerics unchanged: per-step exact power-of-2 renorm with one-step lag,
// PAD chain decoupled analytically. cp.async 16-step double-buffered
// emission pipeline (role-0 warp issues/waits; team barrier publishes).

#define KK 48
#define TT 1024
#define BB 512
#define CH 16
#define NCHUNK (TT / CH)
#define PAD_TAG 45
#define STOP_TAG 47
#define NEGV (-10000.0f)
#define LOG2E 1.4426950408889634f
#define LN2F 0.6931471805599453f

typedef unsigned long long ull;

__device__ __forceinline__ float ex2(float x) {
    float r; asm("ex2.approx.f32 %0, %1;" : "=f"(r) : "f"(x)); return r;
}
__device__ __forceinline__ float lg2(float x) {
    float r; asm("lg2.approx.f32 %0, %1;" : "=f"(r) : "f"(x)); return r;
}
__device__ __forceinline__ ull pk2(float lo, float hi) {
    ull r;
    asm("mov.b64 %0, {%1, %2};" : "=l"(r) : "f"(lo), "f"(hi));
    return r;
}
__device__ __forceinline__ void upk2(float& lo, float& hi, ull v) {
    asm("mov.b64 {%0, %1}, %2;" : "=f"(lo), "=f"(hi) : "l"(v));
}
__device__ __forceinline__ void ffma2(ull& acc, ull a, ull b) {
    asm("fma.rn.f32x2 %0, %1, %2, %0;" : "+l"(acc) : "l"(a), "l"(b));
}
__device__ __forceinline__ ull add2(ull a, ull b) {
    ull r;
    asm("add.rn.f32x2 %0, %1, %2;" : "=l"(r) : "l"(a), "l"(b));
    return r;
}
__device__ __forceinline__ void cpasync16(uint32_t saddr, const void* gaddr) {
    asm volatile("cp.async.cg.shared.global [%0], [%1], 16;"
                 :: "r"(saddr), "l"(gaddr));
}
__device__ __forceinline__ void cpcommit() {
    asm volatile("cp.async.commit_group;");
}
__device__ __forceinline__ void cpwait1() {
    asm volatile("cp.async.wait_group 1;");
}
__device__ __forceinline__ void team_bar(int id) {
    asm volatile("bar.sync %0, 64;" :: "r"(id) : "memory");
}

__global__ __launch_bounds__(256, 1)
void crf_fwd_kernel(const float* __restrict__ h_tag,
                    const float* __restrict__ mask,
                    const float* __restrict__ trans,
                    float* __restrict__ out) {
    __shared__ __align__(16) float trs[KK * KK];
    __shared__ __align__(16) float pd[4][96];            // duplicated p pairs
    __shared__ __align__(16) ull   part[4][2][2][32];    // [team][slot][role][lane]
    __shared__ __align__(16) float sm_em[4][2][CH * KK]; // [team][buf]
    __shared__ __align__(16) float sm_mk[4][2][CH];

    const int tid  = threadIdx.x;
    const int wid  = tid >> 5;
    const int lane = tid & 31;
    const int team = wid >> 1;
    const int role = wid & 1;
    const int b    = blockIdx.x * 4 + team;
    const int barid = 1 + team;

    const float* emb = h_tag + (size_t)b * TT * KK;
    const float* mkb = mask + (size_t)b * TT;

    // ---- emission/mask chunk prefetch (role-0 warp of each team) ----
    auto issue_chunk = [&](int cc) {
        const float* src = emb + cc * (CH * KK);
        uint32_t dst = (uint32_t)__cvta_generic_to_shared(&sm_em[team][cc & 1][0]);
#pragma unroll
        for (int it = 0; it < (CH * KK) / (32 * 4); ++it) {   // 6 iters
            int off = (it * 32 + lane) * 4;
            cpasync16(dst + (uint32_t)off * 4u, src + off);
        }
        if (lane < CH / 4) {
            uint32_t md = (uint32_t)__cvta_generic_to_shared(&sm_mk[team][cc & 1][0]);
            cpasync16(md + (uint32_t)lane * 16u, mkb + cc * CH + lane * 4);
        }
        cpcommit();
    };
    if (role == 0) { issue_chunk(0); issue_chunk(1); }

    // Stage trans coalesced into shared (overlaps cp.async flight).
    for (int i = tid; i < KK * KK; i += 256) trs[i] = trans[i];
    __syncthreads();

    const int  i1   = lane;
    const bool has2 = (lane < 16);
    const int  i2   = has2 ? (lane + 32) : 0;   // clamped for safe loads

    // Row sums over all j (for exact init), per-lane rows i1/i2.
    float rs1 = 0.f, rs2 = 0.f, es1 = 0.f, es2 = 0.f;
#pragma unroll
    for (int j = 0; j < KK; ++j) {
        float e1 = ex2(trs[i1 * KK + j] * LOG2E);
        float e2 = has2 ? ex2(trs[i2 * KK + j] * LOG2E) : 0.f;
        rs1 += e1; rs2 += e2;
        if (j == STOP_TAG) { es1 = e1; es2 = e2; }
    }
    // This warp's 24 E-columns: j = role*24 + k. Columns 45,47 underflow to
    // exact 0 (trans[:,PAD] = trans[:,STOP] = -1e4), keeping bodies uniform.
    ull Ep[24];
#pragma unroll
    for (int k = 0; k < 24; ++k) {
        int j = role * 24 + k;
        float e1 = ex2(trs[i1 * KK + j] * LOG2E);
        float e2 = has2 ? ex2(trs[i2 * KK + j] * LOG2E) : 0.f;
        Ep[k] = pk2(e1, e2);
    }
    const float ES1 = ex2(trs[STOP_TAG * KK + i1] * LOG2E);
    const float ES2 = has2 ? ex2(trs[STOP_TAG * KK + i2] * LOG2E) : 0.f;

    // Exact init at group scale C0 = NEG*log2e:
    // p_i(1) = g_i * ( [i != PAD] + rowsum_i - E[i][STOP] )
    const float base1 = ((i1 == PAD_TAG) ? 0.f : 1.f) + rs1 - es1;
    const float base2 = ((has2 && i2 == PAD_TAG) ? 0.f : 1.f) + rs2 - es2;

    float* pdt = pd[team];
    const float* pdr = pdt + role * 48;   // this role's 24 p-pairs

    float p1, p2, padacc;
    int c = 0, eprev;
    {
        float em1 = emb[i1];
        float em2 = has2 ? emb[i2] : 0.f;
        p1 = ex2(em1 * LOG2E) * base1;
        p2 = has2 ? (ex2(em2 * LOG2E) * base2) : 0.f;
        padacc = em2;   // lane 13 (i2 == 45 == PAD) is the meaningful one

        *(ull*)&pdt[2 * i1] = pk2(p1, p1);       // both warps: identical values
        if (has2) *(ull*)&pdt[2 * i2] = pk2(p2, p2);
        float zp = __shfl_sync(0xffffffffu, p1, 0);
        int eb = (__float_as_int(zp) >> 23) & 255;
        eprev = (eb == 0) ? 0 : (eb - 127);
        __syncwarp();
    }

    // ---- cooperative step: half-matvec, exchange, redundant finalize ----
    auto step = [&](const float* __restrict__ eb,
                    const float* __restrict__ mb, int tt) {
        const int slot = tt & 1;
        const float cem1 = eb[tt * KK + i1];
        const float cem2 = eb[tt * KK + i2];
        const bool  m    = (mb[tt] != 0.0f);

        const float ne = -(float)eprev;
        const float g1 = ex2(fmaf(cem1, LOG2E, ne));
        const float g2 = ex2(fmaf(cem2, LOG2E, ne));

        ull q0 = 0ull, q1 = 0ull, q2 = 0ull, q3 = 0ull;
#pragma unroll
        for (int mm = 0; mm < 12; mm += 2) {       // 12 uniform LDS.128
            ulonglong2 pA = *(const ulonglong2*)(pdr + 4 * mm);
            ulonglong2 pB = *(const ulonglong2*)(pdr + 4 * mm + 4);
            ffma2(q0, pA.x, Ep[2 * mm]);
            ffma2(q1, pA.y, Ep[2 * mm + 1]);
            ffma2(q2, pB.x, Ep[2 * mm + 2]);
            ffma2(q3, pB.y, Ep[2 * mm + 3]);
        }
        ull qs = add2(add2(q0, q1), add2(q2, q3));

        part[team][slot][role][lane] = qs;         // STS.64
        team_bar(barid);
        qs = add2(qs, part[team][slot][role ^ 1][lane]);   // LDS.64 + add

        float qa, qb; upk2(qa, qb, qs);
        p1 = m ? (qa * g1) : p1;
        p2 = m ? (qb * g2) : p2;
        padacc += m ? cem2 : 0.f;
        c      += m ? eprev : 0;

        // Lagged exponent proxy (identical in both warps).
        const float zp = __shfl_sync(0xffffffffu, p1, 0);

        *(ull*)&pdt[2 * i1] = pk2(p1, p1);         // duplicate identical store
        if (has2) *(ull*)&pdt[2 * i2] = pk2(p2, p2);
        __syncwarp();

        const int eb2 = (__float_as_int(zp) >> 23) & 255;
        eprev = (eb2 == 0) ? 0 : (eb2 - 127);
    };

    // ---- chunk 0 (steps 1..15; step 0 handled by init) ----
    {
        if (role == 0) cpwait1();
        team_bar(barid);                 // publish chunk 0 to role-1 warp
        const float* eb = sm_em[team][0];
        const float* mb = sm_mk[team][0];
#pragma unroll 1
        for (int tt = 1; tt < CH; ++tt) step(eb, mb, tt);
        if (role == 0) issue_chunk(2);
    }

    // ---- chunks 1..63 ----
#pragma unroll 1
    for (int cc = 1; cc < NCHUNK; ++cc) {
        if (role == 0) cpwait1();
        team_bar(barid);                 // publish chunk cc
        const int buf = cc & 1;
        const float* eb = sm_em[team][buf];
        const float* mb = sm_mk[team][buf];
#pragma unroll 1
        for (int tt = 0; tt < CH; ++tt) step(eb, mb, tt);
        if (role == 0 && cc + 2 < NCHUNK) issue_chunk(cc + 2);
    }

    // ---- final: lse_j(score_j + trans[STOP][j]) at scale C, merged with
    //      the analytic PAD chain (+ trans[STOP][PAD] = NEG). role 0 writes.
    if (role == 0) {
        float s = p1 * ES1 + (has2 ? p2 * ES2 : 0.f);
#pragma unroll
        for (int o = 16; o > 0; o >>= 1)
            s += __shfl_xor_sync(0xffffffffu, s, o);

        const float C     = NEGV * LOG2E + (float)c;
        const float main2 = C + lg2(s);
        const float padv  = __shfl_sync(0xffffffffu, padacc, 13);
        const float pad2  = (padv + NEGV) * LOG2E;
        const float hi = fmaxf(main2, pad2);
        const float lo = fminf(main2, pad2);
        const float ans2 = hi + lg2(1.0f + ex2(lo - hi));

        if (lane == 0) out[b] = ans2 * LN2F;
    }
}

extern "C" void kernel_launch(void* const* d_in, const int* in_sizes, int n_in,
                              void* d_out, int out_size) {
    const float* h_tag = (const float*)d_in[0];
    const float* mask  = (const float*)d_in[1];
    const float* trans = (const float*)d_in[2];
    float* out = (float*)d_out;
    (void)in_sizes; (void)n_in; (void)out_size;
    crf_fwd_kernel<<<BB / 4, 256>>>(h_tag, mask, trans, out);
}

// round 8
// speedup vs baseline: 1.6716x; 1.4595x over previous
#include <cuda_runtime.h>
#include <cstdint>

// CRF forward partition function, linear-domain reformulation, R8.
// Base = R3 (best: 152.4us, single-warp-per-batch intra-warp scan).
// R8 chain surgery (no structural change, no new synchronization):
//  * __syncwarp hoisted to top-of-step: the prior store's drain + sync
//    latency overlaps this step's emission LDS flight (issued just before).
//  * tt loop unrolled x2 (body ~3.5KB < 6KB L0 I$): halves loop overhead,
//    lets ptxas schedule across step boundaries.
//  * Packed finalize: one mul.rn.f32x2 (q * packed g) replaces unpack+2 FMUL.
// Numerics unchanged: per-step exact power-of-2 renorm with one-step lag,
// PAD chain decoupled analytically, cp.async 16-step double-buffered feed.

#define KK 48
#define TT 1024
#define BB 512
#define CH 16
#define NCHUNK (TT / CH)
#define PAD_TAG 45
#define STOP_TAG 47
#define NEGV (-10000.0f)
#define LOG2E 1.4426950408889634f
#define LN2F 0.6931471805599453f

typedef unsigned long long ull;

__device__ __forceinline__ float ex2(float x) {
    float r; asm("ex2.approx.f32 %0, %1;" : "=f"(r) : "f"(x)); return r;
}
__device__ __forceinline__ float lg2(float x) {
    float r; asm("lg2.approx.f32 %0, %1;" : "=f"(r) : "f"(x)); return r;
}
__device__ __forceinline__ ull pk2(float lo, float hi) {
    ull r;
    asm("mov.b64 %0, {%1, %2};" : "=l"(r) : "f"(lo), "f"(hi));
    return r;
}
__device__ __forceinline__ void upk2(float& lo, float& hi, ull v) {
    asm("mov.b64 {%0, %1}, %2;" : "=f"(lo), "=f"(hi) : "l"(v));
}
__device__ __forceinline__ void ffma2(ull& acc, ull a, ull b) {
    asm("fma.rn.f32x2 %0, %1, %2, %0;" : "+l"(acc) : "l"(a), "l"(b));
}
__device__ __forceinline__ ull add2(ull a, ull b) {
    ull r;
    asm("add.rn.f32x2 %0, %1, %2;" : "=l"(r) : "l"(a), "l"(b));
    return r;
}
__device__ __forceinline__ ull mul2(ull a, ull b) {
    ull r;
    asm("mul.rn.f32x2 %0, %1, %2;" : "=l"(r) : "l"(a), "l"(b));
    return r;
}
__device__ __forceinline__ void cpasync16(uint32_t saddr, const void* gaddr) {
    asm volatile("cp.async.cg.shared.global [%0], [%1], 16;"
                 :: "r"(saddr), "l"(gaddr));
}
__device__ __forceinline__ void cpcommit() {
    asm volatile("cp.async.commit_group;");
}
__device__ __forceinline__ void cpwait1() {
    asm volatile("cp.async.wait_group 1;");
}

__global__ __launch_bounds__(128, 1)
void crf_fwd_kernel(const float* __restrict__ h_tag,
                    const float* __restrict__ mask,
                    const float* __restrict__ trans,
                    float* __restrict__ out) {
    __shared__ __align__(16) float trs[KK * KK];
    __shared__ __align__(16) float pd[4][96];              // duplicated p pairs
    __shared__ __align__(16) float sm_em[4][2][CH * KK];   // emission chunks
    __shared__ __align__(16) float sm_mk[4][2][CH];        // mask chunks

    const int tid  = threadIdx.x;
    const int wid  = tid >> 5;
    const int lane = tid & 31;
    const int b    = blockIdx.x * 4 + wid;

    const float* emb = h_tag + (size_t)b * TT * KK;
    const float* mkb = mask + (size_t)b * TT;

    // ---- deep prefetch: issue chunks 0 and 1 immediately ----
    auto issue_chunk = [&](int cc) {
        const float* src = emb + cc * (CH * KK);
        uint32_t dst = (uint32_t)__cvta_generic_to_shared(&sm_em[wid][cc & 1][0]);
#pragma unroll
        for (int it = 0; it < (CH * KK) / (32 * 4); ++it) {   // 6 iters
            int off = (it * 32 + lane) * 4;                   // float index
            cpasync16(dst + (uint32_t)off * 4u, src + off);
        }
        if (lane < CH / 4) {
            uint32_t md = (uint32_t)__cvta_generic_to_shared(&sm_mk[wid][cc & 1][0]);
            cpasync16(md + (uint32_t)lane * 16u, mkb + cc * CH + lane * 4);
        }
        cpcommit();
    };
    issue_chunk(0);
    issue_chunk(1);

    // Stage trans coalesced into shared (overlaps cp.async flight).
    for (int i = tid; i < KK * KK; i += 128) trs[i] = trans[i];
    __syncthreads();

    const int  i1   = lane;
    const bool has2 = (lane < 16);
    const int  i2   = has2 ? (lane + 32) : 0;   // clamped for safe loads

    // E rows in registers: Ep[j] = packed(exp(trans[i1][j]), exp(trans[i2][j]))
    ull Ep[KK - 1];                             // j = 0..46 (47 never used)
    float rs1 = 0.f, rs2 = 0.f, es1 = 0.f, es2 = 0.f;
#pragma unroll
    for (int j = 0; j < KK; ++j) {
        float e1 = ex2(trs[i1 * KK + j] * LOG2E);
        float e2 = has2 ? ex2(trs[i2 * KK + j] * LOG2E) : 0.f;
        if (j < KK - 1) Ep[j] = pk2(e1, e2);
        rs1 += e1; rs2 += e2;
        if (j == STOP_TAG) { es1 = e1; es2 = e2; }
    }
    const float ES1 = ex2(trs[STOP_TAG * KK + i1] * LOG2E);
    const float ES2 = has2 ? ex2(trs[STOP_TAG * KK + i2] * LOG2E) : 0.f;

    // Exact init at group scale C0 = NEG*log2e:
    // p_i(1) = g_i * ( [i != PAD] + rowsum_i - E[i][STOP] )
    const float base1 = ((i1 == PAD_TAG) ? 0.f : 1.f) + rs1 - es1;
    const float base2 = ((has2 && i2 == PAD_TAG) ? 0.f : 1.f) + rs2 - es2;

    float* pdw = pd[wid];

    float p1, p2, padacc;
    int c = 0, eprev;
    {
        float em1 = emb[i1];
        float em2 = has2 ? emb[i2] : 0.f;
        p1 = ex2(em1 * LOG2E) * base1;
        p2 = has2 ? (ex2(em2 * LOG2E) * base2) : 0.f;
        padacc = em2;   // lane 13 (i2 == 45 == PAD) is the meaningful one

        *(ull*)&pdw[2 * i1] = pk2(p1, p1);
        if (has2) *(ull*)&pdw[2 * i2] = pk2(p2, p2);
        float zp = __shfl_sync(0xffffffffu, p1, 0);
        int eb = (__float_as_int(zp) >> 23) & 255;
        eprev = (eb == 0) ? 0 : (eb - 127);
        // NOTE: no syncwarp here -- the first step's top-of-step syncwarp
        // guards these stores before the first p reload.
    }

    // ---- scan step: emission LDS first, then sync, then p reload+matvec.
    //      The prior store's visibility drain overlaps the emission flight.
    auto step = [&](const float* __restrict__ embuf,
                    const float* __restrict__ mkbuf, int tt) {
        // 1) this step's inputs (independent of pd)
        const float cem1 = embuf[tt * KK + i1];
        const float cem2 = embuf[tt * KK + i2];
        const float cmk  = mkbuf[tt];

        // 2) guard: prior p store -> this step's p reload
        __syncwarp();

        // 3) growth factors (MUFU latency hides under the p LDS flight)
        const bool  m  = (cmk != 0.0f);
        const float ne = -(float)eprev;
        const float g1 = ex2(fmaf(cem1, LOG2E, ne));
        const float g2 = ex2(fmaf(cem2, LOG2E, ne));

        // 4) matvec
        ull q0 = 0ull, q1 = 0ull, q2 = 0ull, q3 = 0ull;
#pragma unroll
        for (int j = 0; j < 44; j += 4) {
            ulonglong2 pA = *(const ulonglong2*)(pdw + 2 * j);
            ulonglong2 pB = *(const ulonglong2*)(pdw + 2 * j + 4);
            ffma2(q0, pA.x, Ep[j]);
            ffma2(q1, pA.y, Ep[j + 1]);
            ffma2(q2, pB.x, Ep[j + 2]);
            ffma2(q3, pB.y, Ep[j + 3]);
        }
        {   // tail: j = 44 and j = 46 (cols 45/PAD, 47/STOP are exactly 0)
            ull p44 = *(const ull*)(pdw + 88);
            ull p46 = *(const ull*)(pdw + 92);
            ffma2(q0, p44, Ep[44]);
            ffma2(q1, p46, Ep[46]);
        }

        // 5) finalize: packed tree + single packed multiply by (g1,g2)
        const ull qs = mul2(add2(add2(q0, q1), add2(q2, q3)), pk2(g1, g2));
        float qa, qb; upk2(qa, qb, qs);

        p1 = m ? qa : p1;
        p2 = m ? qb : p2;
        padacc += m ? cem2 : 0.f;
        c      += m ? eprev : 0;

        // 6) lagged exponent proxy (consumed next step; latency hidden)
        const float zp = __shfl_sync(0xffffffffu, p1, 0);

        // 7) store new p (guarded by NEXT step's top syncwarp)
        *(ull*)&pdw[2 * i1] = pk2(p1, p1);
        if (has2) *(ull*)&pdw[2 * i2] = pk2(p2, p2);

        const int eb2 = (__float_as_int(zp) >> 23) & 255;
        eprev = (eb2 == 0) ? 0 : (eb2 - 127);
    };

    // ---- chunk 0 (steps 1..15; step 0 handled by init) ----
    {
        cpwait1();        // group 0 complete (only group 1 may remain pending)
        __syncwarp();     // publish chunk 0 across lanes
        const float* embuf = sm_em[wid][0];
        const float* mkbuf = sm_mk[wid][0];
#pragma unroll 2
        for (int tt = 1; tt < CH; ++tt) step(embuf, mkbuf, tt);
        issue_chunk(2);
    }

    // ---- chunks 1..63 ----
#pragma unroll 1
    for (int cc = 1; cc < NCHUNK; ++cc) {
        cpwait1();        // chunk cc resident (only cc+1 may remain pending)
        __syncwarp();     // publish chunk cc across lanes
        const int buf = cc & 1;
        const float* embuf = sm_em[wid][buf];
        const float* mkbuf = sm_mk[wid][buf];
#pragma unroll 2
        for (int tt = 0; tt < CH; ++tt) step(embuf, mkbuf, tt);
        if (cc + 2 < NCHUNK) issue_chunk(cc + 2);
    }

    // ---- final: lse_j(score_j + trans[STOP][j]) at scale C, merged with
    //      the analytic PAD chain (+ trans[STOP][PAD] = NEG). ----
    float s = p1 * ES1 + (has2 ? p2 * ES2 : 0.f);
#pragma unroll
    for (int o = 16; o > 0; o >>= 1)
        s += __shfl_xor_sync(0xffffffffu, s, o);

    const float C     = NEGV * LOG2E + (float)c;
    const float main2 = C + lg2(s);
    const float padv  = __shfl_sync(0xffffffffu, padacc, 13);
    const float pad2  = (padv + NEGV) * LOG2E;
    const float hi = fmaxf(main2, pad2);
    const float lo = fminf(main2, pad2);
    const float ans2 = hi + lg2(1.0f + ex2(lo - hi));

    if (lane == 0) out[b] = ans2 * LN2F;
}

extern "C" void kernel_launch(void* const* d_in, const int* in_sizes, int n_in,
                              void* d_out, int out_size) {
    const float* h_tag = (const float*)d_in[0];
    const float* mask  = (const float*)d_in[1];
    const float* trans = (const float*)d_in[2];
    float* out = (float*)d_out;
    (void)in_sizes; (void)n_in; (void)out_size;
    crf_fwd_kernel<<<BB / 4, 128>>>(h_tag, mask, trans, out);
}

// round 9
// speedup vs baseline: 1.9054x; 1.1399x over previous
#include <cuda_runtime.h>
#include <cstdint>

// CRF forward partition function, linear-domain reformulation, R9.
// Base = R3/R8 structure (single warp per batch, cp.async-fed scan).
// R9 change: j-PACKED matvec. q_i = sum_m ffma2(pack(E[i][2m],E[i][2m+1]),
// pack(p_2m, p_2m+1)) + horizontal add. p stored UNduplicated (48 floats):
// per-lane p traffic drops 368B -> 192B/step (12 batched LDS.128), halving
// the shared-crossbar bytes that ncu shows as the top pipe (L1 60%).
// E columns 45 (PAD) and 47 (STOP) are forced to exact zero at build time
// (replaces the old j-skip; also removes an inf-inf hazard in the init
// rowsum). 8 independent FFMA2 accumulator chains (2 rows x 4).
// Numerics otherwise unchanged: per-step exact power-of-2 renorm with
// one-step lag, PAD chain decoupled analytically.

#define KK 48
#define TT 1024
#define BB 512
#define CH 16
#define NCHUNK (TT / CH)
#define PAD_TAG 45
#define STOP_TAG 47
#define NEGV (-10000.0f)
#define LOG2E 1.4426950408889634f
#define LN2F 0.6931471805599453f

typedef unsigned long long ull;

__device__ __forceinline__ float ex2(float x) {
    float r; asm("ex2.approx.f32 %0, %1;" : "=f"(r) : "f"(x)); return r;
}
__device__ __forceinline__ float lg2(float x) {
    float r; asm("lg2.approx.f32 %0, %1;" : "=f"(r) : "f"(x)); return r;
}
__device__ __forceinline__ ull pk2(float lo, float hi) {
    ull r;
    asm("mov.b64 %0, {%1, %2};" : "=l"(r) : "f"(lo), "f"(hi));
    return r;
}
__device__ __forceinline__ void upk2(float& lo, float& hi, ull v) {
    asm("mov.b64 {%0, %1}, %2;" : "=f"(lo), "=f"(hi) : "l"(v));
}
__device__ __forceinline__ void ffma2(ull& acc, ull a, ull b) {
    asm("fma.rn.f32x2 %0, %1, %2, %0;" : "+l"(acc) : "l"(a), "l"(b));
}
__device__ __forceinline__ ull add2(ull a, ull b) {
    ull r;
    asm("add.rn.f32x2 %0, %1, %2;" : "=l"(r) : "l"(a), "l"(b));
    return r;
}
__device__ __forceinline__ void cpasync16(uint32_t saddr, const void* gaddr) {
    asm volatile("cp.async.cg.shared.global [%0], [%1], 16;"
                 :: "r"(saddr), "l"(gaddr));
}
__device__ __forceinline__ void cpcommit() {
    asm volatile("cp.async.commit_group;");
}
__device__ __forceinline__ void cpwait1() {
    asm volatile("cp.async.wait_group 1;");
}

__global__ __launch_bounds__(128, 1)
void crf_fwd_kernel(const float* __restrict__ h_tag,
                    const float* __restrict__ mask,
                    const float* __restrict__ trans,
                    float* __restrict__ out) {
    __shared__ __align__(16) float trs[KK * KK];
    __shared__ __align__(16) float pd[4][KK];              // UNduplicated p
    __shared__ __align__(16) float sm_em[4][2][CH * KK];   // emission chunks
    __shared__ __align__(16) float sm_mk[4][2][CH];        // mask chunks

    const int tid  = threadIdx.x;
    const int wid  = tid >> 5;
    const int lane = tid & 31;
    const int b    = blockIdx.x * 4 + wid;

    const float* emb = h_tag + (size_t)b * TT * KK;
    const float* mkb = mask + (size_t)b * TT;

    // ---- deep prefetch: issue chunks 0 and 1 immediately ----
    auto issue_chunk = [&](int cc) {
        const float* src = emb + cc * (CH * KK);
        uint32_t dst = (uint32_t)__cvta_generic_to_shared(&sm_em[wid][cc & 1][0]);
#pragma unroll
        for (int it = 0; it < (CH * KK) / (32 * 4); ++it) {   // 6 iters
            int off = (it * 32 + lane) * 4;                   // float index
            cpasync16(dst + (uint32_t)off * 4u, src + off);
        }
        if (lane < CH / 4) {
            uint32_t md = (uint32_t)__cvta_generic_to_shared(&sm_mk[wid][cc & 1][0]);
            cpasync16(md + (uint32_t)lane * 16u, mkb + cc * CH + lane * 4);
        }
        cpcommit();
    };
    issue_chunk(0);
    issue_chunk(1);

    // Stage trans coalesced into shared (overlaps cp.async flight).
    for (int i = tid; i < KK * KK; i += 128) trs[i] = trans[i];
    __syncthreads();

    const int  i1   = lane;
    const bool has2 = (lane < 16);
    const int  i2   = has2 ? (lane + 32) : 0;   // clamped for safe loads

    // E rows, j-packed: EpA[m] = pack(E[i1][2m], E[i1][2m+1]) etc.
    // Columns 45 (PAD) and 47 (STOP) forced to exact 0 -- keeps p45/p47
    // out of every row's sum (their mass is handled analytically), and
    // makes the init rowsum finite for row 45.
    ull EpA[24], EpB[24];
    float rs1 = 0.f, rs2 = 0.f;
#pragma unroll
    for (int m = 0; m < 24; ++m) {
        const int j0 = 2 * m;          // even: never 45/47
        const int j1 = 2 * m + 1;      // odd: may be 45 or 47
        const bool z1 = (j1 == PAD_TAG) || (j1 == STOP_TAG);
        float eA0 = ex2(trs[i1 * KK + j0] * LOG2E);
        float eA1 = z1 ? 0.f : ex2(trs[i1 * KK + j1] * LOG2E);
        float eB0 = has2 ? ex2(trs[i2 * KK + j0] * LOG2E) : 0.f;
        float eB1 = (has2 && !z1) ? ex2(trs[i2 * KK + j1] * LOG2E) : 0.f;
        EpA[m] = pk2(eA0, eA1);
        EpB[m] = pk2(eB0, eB1);
        rs1 += eA0 + eA1;
        rs2 += eB0 + eB1;
    }
    const float ES1 = ex2(trs[STOP_TAG * KK + i1] * LOG2E);
    const float ES2 = has2 ? ex2(trs[STOP_TAG * KK + i2] * LOG2E) : 0.f;

    // Exact init at group scale C0 = NEG*log2e:
    // p_i(1) = g_i * ( [i != PAD] + sum_{j not in {PAD,STOP}} E[i][j] )
    const float base1 = ((i1 == PAD_TAG) ? 0.f : 1.f) + rs1;
    const float base2 = ((has2 && i2 == PAD_TAG) ? 0.f : 1.f) + rs2;

    float* pdw = pd[wid];

    float p1, p2, padacc;
    int c = 0, eprev;
    {
        float em1 = emb[i1];
        float em2 = has2 ? emb[i2] : 0.f;
        p1 = ex2(em1 * LOG2E) * base1;
        p2 = has2 ? (ex2(em2 * LOG2E) * base2) : 0.f;
        padacc = em2;   // lane 13 (i2 == 45 == PAD) is the meaningful one

        pdw[i1] = p1;
        if (has2) pdw[i2] = p2;
        float zp = __shfl_sync(0xffffffffu, p1, 0);
        int eb = (__float_as_int(zp) >> 23) & 255;
        eprev = (eb == 0) ? 0 : (eb - 127);
        // First step's top-of-step syncwarp guards these stores.
    }

    // ---- scan step: batched p load (12 LDS.128, max MLP), j-packed matvec.
    auto step = [&](const float* __restrict__ embuf,
                    const float* __restrict__ mkbuf, int tt) {
        // 1) this step's inputs (independent of pd)
        const float cem1 = embuf[tt * KK + i1];
        const float cem2 = embuf[tt * KK + i2];
        const float cmk  = mkbuf[tt];

        // 2) guard: prior p store -> this step's p reload
        __syncwarp();

        // 3) batched p-vector load: 48 floats = 12 x LDS.128, all in flight
        ulonglong2 pv[12];
        const ulonglong2* pdv = (const ulonglong2*)pdw;
#pragma unroll
        for (int k = 0; k < 12; ++k) pv[k] = pdv[k];

        // 4) growth factors (MUFU hides under the load flight)
        const bool  m  = (cmk != 0.0f);
        const float ne = -(float)eprev;
        const float g1 = ex2(fmaf(cem1, LOG2E, ne));
        const float g2 = ex2(fmaf(cem2, LOG2E, ne));

        // 5) j-packed matvec: 8 independent FFMA2 chains, 6 deep
        ull a0 = 0ull, a1 = 0ull, a2 = 0ull, a3 = 0ull;
        ull b0 = 0ull, b1 = 0ull, b2 = 0ull, b3 = 0ull;
#pragma unroll
        for (int k = 0; k < 12; k += 2) {
            ffma2(a0, pv[k].x,     EpA[2 * k]);
            ffma2(a1, pv[k].y,     EpA[2 * k + 1]);
            ffma2(a2, pv[k + 1].x, EpA[2 * k + 2]);
            ffma2(a3, pv[k + 1].y, EpA[2 * k + 3]);
            ffma2(b0, pv[k].x,     EpB[2 * k]);
            ffma2(b1, pv[k].y,     EpB[2 * k + 1]);
            ffma2(b2, pv[k + 1].x, EpB[2 * k + 2]);
            ffma2(b3, pv[k + 1].y, EpB[2 * k + 3]);
        }
        const ull qA = add2(add2(a0, a1), add2(a2, a3));
        const ull qB = add2(add2(b0, b1), add2(b2, b3));
        float qalo, qahi, qblo, qbhi;
        upk2(qalo, qahi, qA);
        upk2(qblo, qbhi, qB);
        const float q1 = (qalo + qahi) * g1;   // horizontal add + scale
        const float q2 = (qblo + qbhi) * g2;

        p1 = m ? q1 : p1;
        p2 = m ? q2 : p2;
        padacc += m ? cem2 : 0.f;
        c      += m ? eprev : 0;

        // 6) lagged exponent proxy (consumed next step; latency hidden)
        const float zp = __shfl_sync(0xffffffffu, p1, 0);

        // 7) store new p unduplicated (guarded by NEXT step's top syncwarp)
        pdw[i1] = p1;
        if (has2) pdw[i2] = p2;

        const int eb2 = (__float_as_int(zp) >> 23) & 255;
        eprev = (eb2 == 0) ? 0 : (eb2 - 127);
    };

    // ---- chunk 0 (steps 1..15; step 0 handled by init) ----
    {
        cpwait1();        // group 0 complete (only group 1 may remain pending)
        __syncwarp();     // publish chunk 0 across lanes
        const float* embuf = sm_em[wid][0];
        const float* mkbuf = sm_mk[wid][0];
#pragma unroll 2
        for (int tt = 1; tt < CH; ++tt) step(embuf, mkbuf, tt);
        issue_chunk(2);
    }

    // ---- chunks 1..63 ----
#pragma unroll 1
    for (int cc = 1; cc < NCHUNK; ++cc) {
        cpwait1();        // chunk cc resident (only cc+1 may remain pending)
        __syncwarp();     // publish chunk cc across lanes
        const int buf = cc & 1;
        const float* embuf = sm_em[wid][buf];
        const float* mkbuf = sm_mk[wid][buf];
#pragma unroll 2
        for (int tt = 0; tt < CH; ++tt) step(embuf, mkbuf, tt);
        if (cc + 2 < NCHUNK) issue_chunk(cc + 2);
    }

    // ---- final: lse_j(score_j + trans[STOP][j]) at scale C, merged with
    //      the analytic PAD chain (+ trans[STOP][PAD] = NEG). ----
    float s = p1 * ES1 + (has2 ? p2 * ES2 : 0.f);
#pragma unroll
    for (int o = 16; o > 0; o >>= 1)
        s += __shfl_xor_sync(0xffffffffu, s, o);

    const float C     = NEGV * LOG2E + (float)c;
    const float main2 = C + lg2(s);
    const float padv  = __shfl_sync(0xffffffffu, padacc, 13);
    const float pad2  = (padv + NEGV) * LOG2E;
    const float hi = fmaxf(main2, pad2);
    const float lo = fminf(main2, pad2);
    const float ans2 = hi + lg2(1.0f + ex2(lo - hi));

    if (lane == 0) out[b] = ans2 * LN2F;
}

extern "C" void kernel_launch(void* const* d_in, const int* in_sizes, int n_in,
                              void* d_out, int out_size) {
    const float* h_tag = (const float*)d_in[0];
    const float* mask  = (const float*)d_in[1];
    const float* trans = (const float*)d_in[2];
    float* out = (float*)d_out;
    (void)in_sizes; (void)n_in; (void)out_size;
    crf_fwd_kernel<<<BB / 4, 128>>>(h_tag, mask, trans, out);
}